// round 13
// baseline (speedup 1.0000x reference)
#include <cuda_runtime.h>
#include <cuda_bf16.h>
#include <cstdint>

// NoiseFilter, exact closed form (validated R3-R12, rel_err ~3e-7):
//   taps: ir0[j] = (1/128)(amp0 + 2*sum_{k=1..63} amp_k cos(pi*k*j/64) + amp64*(-1)^j)
//         h[j]   = ir0[j] * 0.5*(1+cos(pi*j/64)),  j = 0..63
//   s[t] = 2*u[t]-1,  Z[192..255]=0, Z[256+t]=s[t]
//   out[tau] = sum_{d=0}^{63} h[d] * ( Z[256+tau-d] + Z[tau+d] )
// R13 restructure: 8 outputs/thread, 8 pairs/block (1 warp of window traffic
// per pair instead of 2 -> halves the dominant L1 wavefront cost).
// Zb[p][Q] stores Z[192 + 4Q ..] as float4 quads under the quad swizzle
// SQ(Q) = Q ^ ((Q>>3)&1), which makes stride-2-quad lane patterns (from the
// 8-output tiling) conflict-free. Tail term (Z[tau+d]) active only for
// output groups tau0 >= 192 (r >= 24): those lanes are packed into warps 6-7.

#define PAIRS   8
#define THREADS 256
#define ZQ      82             // quads per pair: Zb floats [0,328) = Z[192,520)
#define PI64    0.04908738521234052f

#define SQ(x) ((x) ^ (((x) >> 3) & 1))   // quad-bank swizzle

#define PACK2(dst, lo, hi) \
    asm("mov.b64 %0, {%1, %2};" : "=l"(dst) \
        : "r"(__float_as_uint(lo)), "r"(__float_as_uint(hi)))
#define FMA2(acc, a, b) \
    asm("fma.rn.f32x2 %0, %1, %2, %0;" : "+l"(acc) : "l"(a), "l"(b))
#define ADD2(dst, a, b) \
    asm("add.rn.f32x2 %0, %1, %2;" : "=l"(dst) : "l"(a), "l"(b))
#define UNPACK2(lo, hi, v) \
    asm("mov.b64 {%0, %1}, %2;" : "=r"(lo), "=r"(hi) : "l"(v))

union UQ { float4 f; uint64_t u[2]; };   // u[0]=(x,y), u[1]=(z,w)

__global__ __launch_bounds__(THREADS)
void noisefilter_kernel(const float* __restrict__ amp,    // [65536, 65]
                        const float* __restrict__ noise,  // [65536, 256]
                        float*       __restrict__ out)    // [65536, 256]
{
    __shared__ __align__(16) float4   Zb[PAIRS][ZQ];    // swizzled signal quads
    __shared__ __align__(16) uint64_t hd64[PAIRS][64];  // duplicated taps (h,h)
    __shared__ __align__(16) float    a_sh[PAIRS][68];  // 2*amp

    const int tid = threadIdx.x;
    const long long pairBase = (long long)blockIdx.x * PAIRS;

    // deposit / phase-B mapping: warp = pair
    const int dp = tid >> 5;          // pair for deposit & taps
    const int li = tid & 31;          // lane within pair-warp

    // ---- issue global noise loads early (2 quads per thread) ----
    const float4* n4 = (const float4*)noise;
    float4 v1 = n4[(pairBase + dp) * 64 + li];
    float4 v2 = n4[(pairBase + dp) * 64 + 32 + li];

    // ---- phase A: zero quads 0..15 (Z[192..256)); load amp (doubled) ----
    if (tid < 128) {
        int pp = tid >> 4, qz = tid & 15;
        Zb[pp][SQ(qz)] = make_float4(0.f, 0.f, 0.f, 0.f);
    }
    for (int i = tid; i < PAIRS * 65; i += THREADS) {
        int pp = i / 65, k = i - pp * 65;
        a_sh[pp][k] = 2.f * amp[(pairBase + pp) * 65 + k];
    }
    __syncthreads();

    // ---- phase B: deposit s = 2u-1 (quads 16..79); taps via sym-pair DCT ----
    {
        int q1 = 16 + li, q2 = 48 + li;
        Zb[dp][SQ(q1)] = make_float4(2.f*v1.x-1.f, 2.f*v1.y-1.f,
                                     2.f*v1.z-1.f, 2.f*v1.w-1.f);
        Zb[dp][SQ(q2)] = make_float4(2.f*v2.x-1.f, 2.f*v2.y-1.f,
                                     2.f*v2.z-1.f, 2.f*v2.w-1.f);
    }
    {
        const int jj = li;                               // 0..31
        const float4* a4 = (const float4*)a_sh[dp];
        const float a64  = a_sh[dp][64];

        float e, o;
        int m;
        {   // quad 0: k = 0 (DC), 1, 2, 3
            float4 g = a4[0];
            e = 0.5f * g.x + ((jj & 1) ? -0.5f : 0.5f) * a64;
            m = jj;
            o = g.y * __cosf((float)m * PI64);
            m = (m + jj) & 127;
            e = fmaf(g.z, __cosf((float)m * PI64), e);
            m = (m + jj) & 127;
            o = fmaf(g.w, __cosf((float)m * PI64), o);
        }
        #pragma unroll
        for (int i = 1; i < 16; i++) {                   // k = 4i .. 4i+3
            float4 g = a4[i];
            m = (m + jj) & 127; e = fmaf(g.x, __cosf((float)m * PI64), e);
            m = (m + jj) & 127; o = fmaf(g.y, __cosf((float)m * PI64), o);
            m = (m + jj) & 127; e = fmaf(g.z, __cosf((float)m * PI64), e);
            m = (m + jj) & 127; o = fmaf(g.w, __cosf((float)m * PI64), o);
        }
        float c1 = __cosf((float)jj * PI64);
        float hj = (e + o) * (1.f + c1) * (1.f / 256.f); // tap jj
        uint64_t d0; PACK2(d0, hj, hj);
        hd64[dp][jj] = d0;
        if (jj >= 1) {                                   // partner tap 64-jj
            float hp = (e - o) * (1.f - c1) * (1.f / 256.f);
            uint64_t d1; PACK2(d1, hp, hp);
            hd64[dp][64 - jj] = d1;
        } else {                                         // lane 0: tap 32
            // cos(pi*k/2): +1 (k%4==0), 0 (odd), -1 (k%4==2); window = 1
            float e32 = 0.5f * (a_sh[dp][0] + a64);
            #pragma unroll
            for (int k = 2; k <= 62; k += 2)
                e32 += ((k & 2) ? -1.f : 1.f) * a_sh[dp][k];
            float h32 = e32 * (1.f / 256.f);
            uint64_t d2; PACK2(d2, h32, h32);
            hd64[dp][32] = d2;
        }
    }
    __syncthreads();

    // ---- phase C: convolution, 8 outputs/thread ----
    // tid -> (p, r): r<24 (tail-free) fills warps 0..5; r>=24 warps 6..7.
    int p, r;
    if (tid < 192) { p = tid / 24;      r = tid % 24; }
    else           { int t = tid - 192; p = t >> 3;   r = 24 + (t & 7); }

    {
        const float4*     Zp = (const float4*)(Zb[p]);
        const ulonglong2* H2 = (const ulonglong2*)(hd64[p]);

        uint64_t o01 = 0ull, o23 = 0ull, o45 = 0ull, o67 = 0ull;

        // A window (causal): quads Qlo..Qhi = (2r+15-dq .. 2r+17-dq)
        UQ Qmid, Qhi;
        Qmid.f = Zp[SQ(2*r + 16)];
        Qhi.f  = Zp[SQ(2*r + 17)];
        uint64_t P_m_yz, P_mw_hx, P_h_yz;
        PACK2(P_m_yz,  Qmid.f.y, Qmid.f.z);
        PACK2(P_mw_hx, Qmid.f.w, Qhi.f.x);
        PACK2(P_h_yz,  Qhi.f.y,  Qhi.f.z);

        if (r < 24) {
            #pragma unroll
            for (int dq = 0; dq < 16; dq++) {
                const ulonglong2 Hp = H2[2*dq];      // (h0,h0),(h1,h1)
                const ulonglong2 Hq = H2[2*dq + 1];  // (h2,h2),(h3,h3)
                UQ Qlo; Qlo.f = Zp[SQ(2*r + 15 - dq)];
                uint64_t P_l_yz, P_lw_mx;
                PACK2(P_l_yz,  Qlo.f.y, Qlo.f.z);
                PACK2(P_lw_mx, Qlo.f.w, Qmid.f.x);
                // e=0 (d=4dq):   f = 4,6,8,10
                FMA2(o01, Hp.x, Qmid.u[0]); FMA2(o23, Hp.x, Qmid.u[1]);
                FMA2(o45, Hp.x, Qhi.u[0]);  FMA2(o67, Hp.x, Qhi.u[1]);
                // e=1: f = 3,5,7,9
                FMA2(o01, Hp.y, P_lw_mx);   FMA2(o23, Hp.y, P_m_yz);
                FMA2(o45, Hp.y, P_mw_hx);   FMA2(o67, Hp.y, P_h_yz);
                // e=2: f = 2,4,6,8
                FMA2(o01, Hq.x, Qlo.u[1]);  FMA2(o23, Hq.x, Qmid.u[0]);
                FMA2(o45, Hq.x, Qmid.u[1]); FMA2(o67, Hq.x, Qhi.u[0]);
                // e=3: f = 1,3,5,7
                FMA2(o01, Hq.y, P_l_yz);    FMA2(o23, Hq.y, P_lw_mx);
                FMA2(o45, Hq.y, P_m_yz);    FMA2(o67, Hq.y, P_mw_hx);
                // rotate window + carried packs
                Qhi = Qmid; Qmid = Qlo;
                P_h_yz = P_m_yz; P_mw_hx = P_lw_mx; P_m_yz = P_l_yz;
            }
        } else {
            // tail: + sum h[d] * Z[tau+d];  V quads = (2r-48+dq .. 2r-46+dq)
            UQ Vlo, Vmid, Vhi;
            Vlo.f  = Zp[SQ(2*r - 48)];
            Vmid.f = Zp[SQ(2*r - 47)];
            Vhi.f  = Zp[SQ(2*r - 46)];
            #pragma unroll
            for (int dq = 0; dq < 16; dq++) {
                const ulonglong2 Hp = H2[2*dq];
                const ulonglong2 Hq = H2[2*dq + 1];
                UQ Qlo; Qlo.f = Zp[SQ(2*r + 15 - dq)];
                uint64_t P_l_yz, P_lw_mx;
                PACK2(P_l_yz,  Qlo.f.y, Qlo.f.z);
                PACK2(P_lw_mx, Qlo.f.w, Qmid.f.x);
                // V-side packs (fresh each iter; registers rotate below)
                uint64_t V_l_yz, V_lw_mx, V_m_yz, V_mw_hx, V_h_yz;
                PACK2(V_l_yz,  Vlo.f.y,  Vlo.f.z);
                PACK2(V_lw_mx, Vlo.f.w,  Vmid.f.x);
                PACK2(V_m_yz,  Vmid.f.y, Vmid.f.z);
                PACK2(V_mw_hx, Vmid.f.w, Vhi.f.x);
                PACK2(V_h_yz,  Vhi.f.y,  Vhi.f.z);
                uint64_t S0, S1, S2, S3;
                // e=0: A f=4,6,8,10 ; V g=0,2,4,6
                ADD2(S0, Qmid.u[0], Vlo.u[0]);  ADD2(S1, Qmid.u[1], Vlo.u[1]);
                ADD2(S2, Qhi.u[0],  Vmid.u[0]); ADD2(S3, Qhi.u[1],  Vmid.u[1]);
                FMA2(o01, Hp.x, S0); FMA2(o23, Hp.x, S1);
                FMA2(o45, Hp.x, S2); FMA2(o67, Hp.x, S3);
                // e=1: A f=3,5,7,9 ; V g=1,3,5,7
                ADD2(S0, P_lw_mx, V_l_yz);  ADD2(S1, P_m_yz,  V_lw_mx);
                ADD2(S2, P_mw_hx, V_m_yz);  ADD2(S3, P_h_yz,  V_mw_hx);
                FMA2(o01, Hp.y, S0); FMA2(o23, Hp.y, S1);
                FMA2(o45, Hp.y, S2); FMA2(o67, Hp.y, S3);
                // e=2: A f=2,4,6,8 ; V g=2,4,6,8
                ADD2(S0, Qlo.u[1],  Vlo.u[1]);  ADD2(S1, Qmid.u[0], Vmid.u[0]);
                ADD2(S2, Qmid.u[1], Vmid.u[1]); ADD2(S3, Qhi.u[0],  Vhi.u[0]);
                FMA2(o01, Hq.x, S0); FMA2(o23, Hq.x, S1);
                FMA2(o45, Hq.x, S2); FMA2(o67, Hq.x, S3);
                // e=3: A f=1,3,5,7 ; V g=3,5,7,9
                ADD2(S0, P_l_yz,  V_lw_mx); ADD2(S1, P_lw_mx, V_m_yz);
                ADD2(S2, P_m_yz,  V_mw_hx); ADD2(S3, P_mw_hx, V_h_yz);
                FMA2(o01, Hq.y, S0); FMA2(o23, Hq.y, S1);
                FMA2(o45, Hq.y, S2); FMA2(o67, Hq.y, S3);
                // rotate A window + carried packs
                Qhi = Qmid; Qmid = Qlo;
                P_h_yz = P_m_yz; P_mw_hx = P_lw_mx; P_m_yz = P_l_yz;
                // rotate V window (slides up)
                Vlo = Vmid; Vmid = Vhi;
                if (dq < 15) Vhi.f = Zp[SQ(2*r - 45 + dq)];
            }
        }

        uint32_t u0, u1, u2, u3, u4, u5, u6, u7;
        UNPACK2(u0, u1, o01); UNPACK2(u2, u3, o23);
        UNPACK2(u4, u5, o45); UNPACK2(u6, u7, o67);
        float4* o4 = (float4*)out + (pairBase + p) * 64 + 2*r;
        o4[0] = make_float4(__uint_as_float(u0), __uint_as_float(u1),
                            __uint_as_float(u2), __uint_as_float(u3));
        o4[1] = make_float4(__uint_as_float(u4), __uint_as_float(u5),
                            __uint_as_float(u6), __uint_as_float(u7));
    }
}

extern "C" void kernel_launch(void* const* d_in, const int* in_sizes, int n_in,
                              void* d_out, int out_size)
{
    const float* amp   = (const float*)d_in[0];   // filter_bank [16,4096,65]
    const float* noise = (const float*)d_in[1];   // noise_u     [16,4096,256]
    float* out = (float*)d_out;                   // [16, 4096*256, 1]

    const int total_pairs = in_sizes[0] / 65;     // 65536
    const int blocks = total_pairs / PAIRS;       // 8192
    noisefilter_kernel<<<blocks, THREADS>>>(amp, noise, out);
}